// round 12
// baseline (speedup 1.0000x reference)
#include <cuda_runtime.h>
#include <cuda_bf16.h>

#define NQ    18
#define NBAT  16
#define NTHR  (NQ * NBAT)   // 288: one thread per (batch, site)

// Sum/difference-basis MPS, forward sweep only (derivation verified R2..R10).
// Site map in pre-distributed form (producers fold the constant products):
//   sd' = z3*dd ; dd' = wx*p + w*sd ; p' = e*p + ey*sd
//   z_i = sd' + q01*p'   (q01 = 2*s0 of site i+1; 2.0 at i=17)
// with z3=c1*c0, w=c1, wx=c1*2s0, ey=-s1*0.5s0, e=-s1  (angles are FULL angles).

__shared__ float4 g_cA[NQ][NBAT];   // {z3, w, wx, ey}
__shared__ float2 g_cB[NQ][NBAT];   // {e, q01}

__global__ void __launch_bounds__(NTHR, 1)
quantum_mps_kernel(const float* __restrict__ in, float* __restrict__ out) {
    const int tid = threadIdx.x;

    // ---- phase 1: one (batch, site) per thread
    {
        const int b = tid / NQ, s = tid % NQ;
        float s0, c0, s1, c1;
        __sincosf(in[b * 36 + s],      &s0, &c0);   // layer 0
        __sincosf(in[b * 36 + 18 + s], &s1, &c1);   // layer 1
        g_cA[s][b] = make_float4(c1 * c0, c1, c1 * (s0 + s0), -s1 * 0.5f * s0);
        g_cB[s][b].x = -s1;
        if (s > 0) g_cB[s - 1][b].y = s0 + s0;      // q01 for previous site
        else       g_cB[NQ - 1][b].y = 2.0f;        // terminator for site 17
    }
    __syncthreads();

    // ---- phase 2: forward sweep + in-loop readout on the HIGHEST warp
    // (hi-wid-first arbiter gives the chain warp issue priority)
    if (tid >= 256 && tid < 256 + NBAT) {
        const int b = tid - 256;
        float sd = 1.0f, dd = 1.0f, p = 0.0f;
        #pragma unroll
        for (int t = 0; t < NQ; t++) {
            const float4 a  = g_cA[t][b];   // {z3, w, wx, ey}
            const float2 cb = g_cB[t][b];   // {e, q01}
            const float nsd = a.x * dd;
            const float ndd = fmaf(a.z, p, a.y * sd);
            const float np  = fmaf(cb.x, p, a.w * sd);
            sd = nsd; dd = ndd; p = np;
            out[b * NQ + t] = fmaf(cb.y, np, nsd);
        }
    }
}

extern "C" void kernel_launch(void* const* d_in, const int* in_sizes, int n_in,
                              void* d_out, int out_size) {
    const float* in  = (const float*)d_in[0];
    float*       out = (float*)d_out;
    quantum_mps_kernel<<<1, NTHR>>>(in, out);
}